// round 2
// baseline (speedup 1.0000x reference)
#include <cuda_runtime.h>
#include <cstdint>
#include <cstddef>

// BacklashNet: out_t = f1 ? (f2 ? lo+ub : lo) : (f2 ? ub : prev)
//   lo = m_lo*x_t + m_lo*c_lo ; ub = m_up*x_t + m_up*c_up
//   f1 = (prev >= lo) ; f2 = (prev <= ub)
// One thread per batch row; SMEM-staged tiles for coalesced global traffic.

#define RPB    64      // rows per block (= threads per block)
#define TT     128     // timesteps per tile
#define STRIDE 130     // padded floats per smem row (520B: 8B aligned, 2-way LDS conflict only)

__device__ __forceinline__ uint32_t smem_u32(const void* p) {
    return (uint32_t)__cvta_generic_to_shared(p);
}
__device__ __forceinline__ void cp_async8(uint32_t dst, const float* src) {
    asm volatile("cp.async.ca.shared.global [%0], [%1], 8;\n" :: "r"(dst), "l"(src));
}
__device__ __forceinline__ void cp_commit() {
    asm volatile("cp.async.commit_group;\n" ::: "memory");
}
__device__ __forceinline__ void cp_wait0() {
    asm volatile("cp.async.wait_group 0;\n" ::: "memory");
}

extern __shared__ float g_smem[];

__global__ __launch_bounds__(RPB, 1)
void backlash_scan_kernel(const float* __restrict__ x,
                          const float* __restrict__ p0,
                          const float* __restrict__ w,
                          float* __restrict__ out,
                          int T)
{
    float* inb0 = g_smem;
    float* inb1 = g_smem + RPB * STRIDE;
    float* outb = g_smem + 2 * RPB * STRIDE;

    const int tid  = threadIdx.x;
    const int row0 = blockIdx.x * RPB;

    // Scalar weights (4 floats, L2/const cached after first block touches them)
    const float m_lo = w[0];
    const float m_up = w[1];
    const float c_lo = w[2];
    const float c_up = w[3];
    // Match reference rounding: products rounded individually, no fma contraction.
    const float k_lo = __fmul_rn(m_lo, c_lo);
    const float k_up = __fmul_rn(m_up, c_up);

    const int ntiles = T / TT;

    // Prologue: stage tile 0 into inb0.
    {
        const float* src = x + (size_t)row0 * T + tid * 2;
        uint32_t dst = smem_u32(inb0) + (uint32_t)(tid * 2) * 4u;
        #pragma unroll 8
        for (int r = 0; r < RPB; ++r)
            cp_async8(dst + (uint32_t)(r * STRIDE) * 4u, src + (size_t)r * T);
        cp_commit();
    }

    float prev = p0[row0 + tid];

    for (int tile = 0; tile < ntiles; ++tile) {
        float* inb = (tile & 1) ? inb1 : inb0;
        float* nxt = (tile & 1) ? inb0 : inb1;

        // Wait for this tile's staging; make it visible to all threads.
        cp_wait0();
        __syncthreads();   // also orders: prev iter's outb reads before this iter's outb writes

        // Fire-and-forget staging of next tile (overlaps with scan below).
        if (tile + 1 < ntiles) {
            const float* src = x + (size_t)row0 * T + (size_t)(tile + 1) * TT + tid * 2;
            uint32_t dst = smem_u32(nxt) + (uint32_t)(tid * 2) * 4u;
            #pragma unroll 8
            for (int r = 0; r < RPB; ++r)
                cp_async8(dst + (uint32_t)(r * STRIDE) * 4u, src + (size_t)r * T);
            cp_commit();
        }

        // Serial scan of this thread's row over the tile.
        const float* xin  = inb  + tid * STRIDE;
        float*       xout = outb + tid * STRIDE;
        #pragma unroll 8
        for (int t = 0; t < TT; ++t) {
            float xv  = xin[t];
            // prev-independent precompute (hoisted above the chain by ptxas)
            float mlx = __fmul_rn(m_lo, xv);
            float upx = __fmul_rn(m_up, xv);
            float lo  = __fadd_rn(mlx, k_lo);
            float ub  = __fadd_rn(upx, k_up);
            // reference summation order for the f1&&f2 case: ((lo + m_up*x) + k_up)
            float both = __fadd_rn(__fadd_rn(lo, upx), k_up);
            // critical chain: FSETP -> FSEL -> FSEL
            bool  f1 = (prev >= lo);
            bool  f2 = (prev <= ub);
            float a  = f2 ? both : lo;
            float b  = f2 ? ub   : prev;
            prev = f1 ? a : b;
            xout[t] = prev;
        }
        __syncthreads();

        // Cooperative coalesced store of the out tile.
        {
            float* dst = out + (size_t)row0 * T + (size_t)tile * TT + tid * 2;
            #pragma unroll 8
            for (int r = 0; r < RPB; ++r) {
                float2 v = *(const float2*)(outb + r * STRIDE + tid * 2);
                *(float2*)(dst + (size_t)r * T) = v;
            }
        }
        // NOTE: top-of-loop __syncthreads orders these reads vs next tile's outb writes.
    }
}

extern "C" void kernel_launch(void* const* d_in, const int* in_sizes, int n_in,
                              void* d_out, int out_size)
{
    const float* x  = (const float*)d_in[0];  // (B, T, 1) fp32
    const float* p0 = (const float*)d_in[1];  // (B, 1, 1) fp32
    const float* w  = (const float*)d_in[2];  // (4,)      fp32
    float* out = (float*)d_out;

    const int B = in_sizes[1];                // 2048
    const int T = in_sizes[0] / B;            // 8192

    const size_t shmem = (size_t)3 * RPB * STRIDE * sizeof(float);  // 99,840 B
    cudaFuncSetAttribute(backlash_scan_kernel,
                         cudaFuncAttributeMaxDynamicSharedMemorySize, (int)shmem);

    backlash_scan_kernel<<<B / RPB, RPB, shmem>>>(x, p0, w, out, T);
}

// round 3
// speedup vs baseline: 5.9715x; 5.9715x over previous
#include <cuda_runtime.h>
#include <cstdint>
#include <cstddef>

// BacklashNet chunk-parallel scan.
// Step map (exact reference semantics):
//   lo = fl(fl(m_lo*x) + fl(m_lo*c_lo)), upx = fl(m_up*x), ub = fl(upx + k_up)
//   f1 = (prev >= lo)            [== sign-exact reference test fl(lo - prev) <= 0]
//   f2 = (fl(prev - upx) <= k_up)[== sign-exact reference test fl(fl(prev-upx)-k_up) <= 0]
//   out = f1 ? (f2 ? fl(fl(lo+upx)+k_up) : lo) : (f2 ? ub : prev)
// Identity branch requires prev in an interval that almost surely empties within a
// few steps -> chunk output becomes provably independent of incoming state.

#define NCHUNK 128   // chunks per row = threads per block
                     // CHUNK = T / NCHUNK (= 64 for T=8192)

struct Wt { float m_lo, m_up, k_lo, k_up; };

__device__ __forceinline__ bool f2_pred(float p, float upx, float k_up) {
    return __fadd_rn(p, -upx) <= k_up;     // fl(p - upx) <= k_up  (monotone in p)
}

__device__ __forceinline__ void mkconst(const Wt& w, float xv,
                                        float& lo, float& upx, float& ub, float& v1) {
    float mlx = __fmul_rn(w.m_lo, xv);
    upx = __fmul_rn(w.m_up, xv);
    lo  = __fadd_rn(mlx, w.k_lo);
    ub  = __fadd_rn(upx, w.k_up);
    v1  = __fadd_rn(__fadd_rn(lo, upx), w.k_up);   // reference's left-assoc sum, both flags set
}

__device__ __forceinline__ float step1(float p, float lo, float upx, float ub,
                                       float v1, float k_up) {
    bool f1 = (p >= lo);
    bool f2 = f2_pred(p, upx, k_up);
    float a = f2 ? v1 : lo;
    float b = f2 ? ub : p;
    return f1 ? a : b;
}

// Largest float strictly below a (a finite).
__device__ __forceinline__ float next_below(float a) {
    unsigned u = __float_as_uint(a);
    if (a > 0.0f)            u -= 1u;
    else if ((u << 1) == 0u) u = 0x80000001u;   // +-0 -> smallest negative denormal
    else                     u += 1u;
    return __uint_as_float(u);
}

__device__ float replay_chunk(const float* __restrict__ xc, float p, Wt w, int n) {
    for (int t = 0; t < n; ++t) {
        float lo, upx, ub, v1;
        mkconst(w, xc[t], lo, upx, ub, v1);
        p = step1(p, lo, upx, ub, v1, w.k_up);
    }
    return p;
}

__global__ __launch_bounds__(NCHUNK)
void backlash_chunks(const float* __restrict__ x,
                     const float* __restrict__ p0,
                     const float* __restrict__ wv,
                     float* __restrict__ out, int T)
{
    __shared__ float s_cv[NCHUNK];   // collapsed end-of-chunk value
    __shared__ int   s_sx[NCHUNK];   // collapse index (CL => never collapsed)
    __shared__ float s_in[NCHUNK];   // resolved incoming prev per chunk

    const int k   = threadIdx.x;
    const int row = blockIdx.x;
    const int CL  = T / NCHUNK;      // 64

    Wt w;
    w.m_lo = wv[0];
    w.m_up = wv[1];
    w.k_lo = __fmul_rn(w.m_lo, wv[2]);
    w.k_up = __fmul_rn(w.m_up, wv[3]);

    const float* xc = x   + (size_t)row * T + (size_t)k * CL;
    float*       oc = out + (size_t)row * T + (size_t)k * CL;

    const float INF = __int_as_float(0x7f800000);

    // ---- Phase 1: interval scan until collapse, then concrete scan ----
    float A = -INF, B = INF;     // sound hull of all possible states
    float p = 0.0f;
    bool  done = false;
    int   s = CL;                // collapse position within chunk

    for (int t4 = 0; t4 < CL; t4 += 4) {
        float4 q = *(const float4*)(xc + t4);
        float xs[4] = {q.x, q.y, q.z, q.w};
        float ov[4];
        #pragma unroll
        for (int j = 0; j < 4; ++j) {
            float lo, upx, ub, v1;
            mkconst(w, xs[j], lo, upx, ub, v1);
            if (!done) {
                // Region reachability tests over [A,B] via endpoint predicate evals
                // (exactly the concrete predicates -> collapse decisions are exact).
                float mAlo = fmaxf(A, lo);
                bool c1 = (mAlo <= B) &&  f2_pred(mAlo, upx, w.k_up);   // f1 & f2 -> v1
                bool c2 = (B >= lo)   && !f2_pred(B,    upx, w.k_up);   // f1 &!f2 -> lo
                bool c3 = (A <  lo)   &&  f2_pred(A,    upx, w.k_up);   // !f1& f2 -> ub
                float ps = fminf(B, next_below(lo));
                bool c4 = (ps >= A)   && !f2_pred(ps,   upx, w.k_up);   // identity survives
                float nA = INF, nB = -INF;
                if (c1) { nA = fminf(nA, v1); nB = fmaxf(nB, v1); }
                if (c2) { nA = fminf(nA, lo); nB = fmaxf(nB, lo); }
                if (c3) { nA = fminf(nA, ub); nB = fmaxf(nB, ub); }
                if (c4) { nA = fminf(nA, A);  nB = fmaxf(nB, ps); }
                A = nA; B = nB;
                if (A == B) { done = true; p = A; s = t4 + j; }
            } else {
                p = step1(p, lo, upx, ub, v1, w.k_up);
            }
            ov[j] = p;
        }
        // Outputs are exact (state-independent) for t >= s.
        if (done) {
            if (s <= t4) {
                *(float4*)(oc + t4) = make_float4(ov[0], ov[1], ov[2], ov[3]);
            } else {
                #pragma unroll
                for (int j = 0; j < 4; ++j)
                    if (t4 + j >= s) oc[t4 + j] = ov[j];
            }
        }
    }

    // ---- Phase 2: inter-chunk resolution ----
    s_cv[k] = p;
    s_sx[k] = s;
    bool all = (bool)__syncthreads_and((int)done);   // block-uniform
    if (all) {
        // Every chunk's output state is prev-independent: O(1) resolution.
        s_in[k] = (k == 0) ? p0[row] : s_cv[k - 1];
    } else {
        // Rare: serialize over chunks, replaying uncollapsed ones.
        if (k == 0) {
            float prev = p0[row];
            const float* xr = x + (size_t)row * T;
            for (int c = 0; c < NCHUNK; ++c) {
                s_in[c] = prev;
                prev = (s_sx[c] < CL) ? s_cv[c]
                                      : replay_chunk(xr + (size_t)c * CL, prev, w, CL);
            }
        }
        __syncthreads();
    }

    // ---- Phase 3: replay the short pre-collapse prefix with the true state ----
    float pin = s_in[k];
    for (int t = 0; t < s; ++t) {
        float lo, upx, ub, v1;
        mkconst(w, xc[t], lo, upx, ub, v1);
        pin = step1(pin, lo, upx, ub, v1, w.k_up);
        oc[t] = pin;
    }
}

extern "C" void kernel_launch(void* const* d_in, const int* in_sizes, int n_in,
                              void* d_out, int out_size)
{
    const float* x  = (const float*)d_in[0];  // (B, T, 1) fp32
    const float* p0 = (const float*)d_in[1];  // (B, 1, 1) fp32
    const float* wv = (const float*)d_in[2];  // (4,)      fp32
    float* out = (float*)d_out;

    const int B = in_sizes[1];      // 2048
    const int T = in_sizes[0] / B;  // 8192

    backlash_chunks<<<B, NCHUNK>>>(x, p0, wv, out, T);
}

// round 5
// speedup vs baseline: 7.8688x; 1.3177x over previous
#include <cuda_runtime.h>
#include <cstdint>
#include <cstddef>

// BacklashNet chunk-parallel scan, SMEM-staged & coalesced.
//   lo = fl(fl(m_lo*x) + fl(m_lo*c_lo)), upx = fl(m_up*x), ub = fl(upx + k_up)
//   f1 = (prev >= lo);  f2 = (fl(prev - upx) <= k_up)
//   out = f1 ? (f2 ? fl(fl(lo+upx)+k_up) : lo) : (f2 ? ub : prev)
// Identity branch needs prev in (ub*, lo): interval-tracked until it provably
// collapses to one value -> chunk outputs become state-independent.

#define NT   256          // threads per block = chunks per row
#define CL   32           // steps per chunk (T = NT*CL = 8192)
#define PAD  36           // floats per chunk in smem (CL+4): 144B stride ->
                          //   16B-aligned & conflict-free for 128-bit LDS/STS

struct Wt { float m_lo, m_up, k_lo, k_up; };

__device__ __forceinline__ uint32_t smem_u32(const void* p) {
    return (uint32_t)__cvta_generic_to_shared(p);
}
__device__ __forceinline__ void cp_async16(uint32_t dst, const float* src) {
    asm volatile("cp.async.ca.shared.global [%0], [%1], 16;\n" :: "r"(dst), "l"(src));
}

__device__ __forceinline__ bool f2_pred(float p, float upx, float k_up) {
    return __fadd_rn(p, -upx) <= k_up;          // fl(p - upx) <= k_up (monotone in p)
}
__device__ __forceinline__ void mkconst(const Wt& w, float xv,
                                        float& lo, float& upx, float& ub, float& v1) {
    float mlx = __fmul_rn(w.m_lo, xv);
    upx = __fmul_rn(w.m_up, xv);
    lo  = __fadd_rn(mlx, w.k_lo);
    ub  = __fadd_rn(upx, w.k_up);
    v1  = __fadd_rn(__fadd_rn(lo, upx), w.k_up); // reference's left-assoc sum
}
__device__ __forceinline__ float step1(float p, float lo, float upx, float ub,
                                       float v1, float k_up) {
    bool f1 = (p >= lo);
    bool f2 = f2_pred(p, upx, k_up);
    float a = f2 ? v1 : lo;
    float b = f2 ? ub : p;
    return f1 ? a : b;
}
__device__ __forceinline__ float next_below(float a) {   // largest float < a
    unsigned u = __float_as_uint(a);
    if (a > 0.0f)            u -= 1u;
    else if ((u << 1) == 0u) u = 0x80000001u;
    else                     u += 1u;
    return __uint_as_float(u);
}

__global__ __launch_bounds__(NT)
void backlash_chunks(const float* __restrict__ x,
                     const float* __restrict__ p0,
                     const float* __restrict__ wv,
                     float* __restrict__ out, int T)
{
    __shared__ float s_buf[NT * PAD];   // in/out aliased row buffer
    __shared__ float s_cv[NT];          // collapsed end-of-chunk value
    __shared__ int   s_sx[NT];          // collapse index (CL => never collapsed)
    __shared__ float s_in[NT];          // fallback: resolved incoming prev

    const int k   = threadIdx.x;
    const int row = blockIdx.x;
    const int F4  = T / (NT * 4);       // float4s per thread in coop copies (= 8)

    Wt w;
    w.m_lo = wv[0];
    w.m_up = wv[1];
    w.k_lo = __fmul_rn(w.m_lo, wv[2]);
    w.k_up = __fmul_rn(w.m_up, wv[3]);

    // ---- Coalesced staged load of the whole row (chunk-padded layout) ----
    {
        const float* src = x + (size_t)row * T;
        const uint32_t sb = smem_u32(s_buf);
        #pragma unroll
        for (int i = 0; i < F4; ++i) {
            int t = i * (NT * 4) + k * 4;
            int c = t / CL, o = t % CL;
            cp_async16(sb + (uint32_t)(c * PAD + o) * 4u, src + t);
        }
        asm volatile("cp.async.commit_group;\n" ::: "memory");
        asm volatile("cp.async.wait_group 0;\n" ::: "memory");
    }
    __syncthreads();

    float* xc = s_buf + k * PAD;        // this thread's chunk (in; becomes out)
    const float INF = __int_as_float(0x7f800000);

    // ---- Phase 1: interval scan until collapse, then concrete scan ----
    float A = -INF, B = INF;
    float p = 0.0f;
    bool  done = false;
    int   s = CL;

    #pragma unroll
    for (int t4 = 0; t4 < CL; t4 += 4) {
        float4 q = *(const float4*)(xc + t4);
        float xs[4] = {q.x, q.y, q.z, q.w};
        float ov[4];
        #pragma unroll
        for (int j = 0; j < 4; ++j) {
            float lo, upx, ub, v1;
            mkconst(w, xs[j], lo, upx, ub, v1);
            if (!done) {
                // Reachability of each region over [A,B]: endpoint evals of the
                // exact concrete predicates -> collapse decisions are exact.
                float mAlo = fmaxf(A, lo);
                bool c1 = (mAlo <= B) &&  f2_pred(mAlo, upx, w.k_up); // f1& f2 -> v1
                bool c2 = (B >= lo)   && !f2_pred(B,    upx, w.k_up); // f1&!f2 -> lo
                bool c3 = (A <  lo)   &&  f2_pred(A,    upx, w.k_up); //!f1& f2 -> ub
                float ps = fminf(B, next_below(lo));
                bool c4 = (ps >= A)   && !f2_pred(ps,   upx, w.k_up); // identity
                float nA = INF, nB = -INF;
                if (c1) { nA = fminf(nA, v1); nB = fmaxf(nB, v1); }
                if (c2) { nA = fminf(nA, lo); nB = fmaxf(nB, lo); }
                if (c3) { nA = fminf(nA, ub); nB = fmaxf(nB, ub); }
                if (c4) { nA = fminf(nA, A);  nB = fmaxf(nB, ps); }
                A = nA; B = nB;
                if (A == B) { done = true; p = A; s = t4 + j; }
            } else {
                p = step1(p, lo, upx, ub, v1, w.k_up);
            }
            ov[j] = p;
        }
        // Write state-independent outputs (t >= s) in place over consumed input.
        if (done) {
            if (s <= t4) {
                *(float4*)(xc + t4) = make_float4(ov[0], ov[1], ov[2], ov[3]);
            } else {
                #pragma unroll
                for (int j = 0; j < 4; ++j)
                    if (t4 + j >= s) xc[t4 + j] = ov[j];
            }
        }
    }

    // ---- Phase 2: inter-chunk resolution ----
    s_cv[k] = p;
    s_sx[k] = s;
    bool all = (bool)__syncthreads_and((int)done);   // block-uniform, is a barrier
    float pin;
    if (all) {
        pin = (k == 0) ? p0[row] : s_cv[k - 1];      // O(1) fast path
    } else {
        if (k == 0) {                                 // rare serial fallback
            float prev = p0[row];
            for (int c = 0; c < NT; ++c) {
                s_in[c] = prev;
                if (s_sx[c] < CL) {
                    prev = s_cv[c];
                } else {                              // chunk untouched in s_buf
                    const float* xr = s_buf + c * PAD;
                    for (int t = 0; t < CL; ++t) {
                        float lo, upx, ub, v1;
                        mkconst(w, xr[t], lo, upx, ub, v1);
                        prev = step1(prev, lo, upx, ub, v1, w.k_up);
                    }
                }
            }
        }
        __syncthreads();
        pin = s_in[k];
    }

    // ---- Phase 3: replay short pre-collapse prefix with the true state ----
    for (int t = 0; t < s; ++t) {
        float lo, upx, ub, v1;
        mkconst(w, xc[t], lo, upx, ub, v1);
        pin = step1(pin, lo, upx, ub, v1, w.k_up);
        xc[t] = pin;
    }
    __syncthreads();

    // ---- Coalesced staged store of the whole row ----
    {
        float* dst = out + (size_t)row * T;
        #pragma unroll
        for (int i = 0; i < F4; ++i) {
            int t = i * (NT * 4) + k * 4;
            int c = t / CL, o = t % CL;
            float4 v = *(const float4*)(s_buf + c * PAD + o);
            *(float4*)(dst + t) = v;
        }
    }
}

extern "C" void kernel_launch(void* const* d_in, const int* in_sizes, int n_in,
                              void* d_out, int out_size)
{
    const float* x  = (const float*)d_in[0];  // (B, T, 1) fp32
    const float* p0 = (const float*)d_in[1];  // (B, 1, 1) fp32
    const float* wv = (const float*)d_in[2];  // (4,)      fp32
    float* out = (float*)d_out;

    const int B = in_sizes[1];      // 2048
    const int T = in_sizes[0] / B;  // 8192  (= NT * CL)

    backlash_chunks<<<B, NT>>>(x, p0, wv, out, T);
}

// round 6
// speedup vs baseline: 10.1047x; 1.2842x over previous
#include <cuda_runtime.h>
#include <cstdint>
#include <cstddef>

// BacklashNet chunk-parallel scan, SMEM-staged & coalesced, lean issue stream.
//   lo = fl(fl(m_lo*x) + fl(m_lo*c_lo)), upx = fl(m_up*x), ub = fl(upx + k_up)
//   f1 = (prev >= lo);  f2 = (fl(prev - upx) <= k_up)
//   out = f1 ? (f2 ? fl(fl(lo+upx)+k_up) : lo) : (f2 ? ub : prev)
// Identity branch needs prev in (ub*, lo): interval-tracked until it provably
// collapses to one value -> chunk outputs become state-independent.

#define NT   256          // threads per block = chunks per row
#define CL   32           // steps per chunk (T = NT*CL = 8192)
#define PAD  36           // smem floats per chunk: 144B stride, 16B-aligned,
                          //   conflict-free for 128-bit LDS/STS

struct Wt { float m_lo, m_up, k_lo, k_up; };

__device__ __forceinline__ uint32_t smem_u32(const void* p) {
    return (uint32_t)__cvta_generic_to_shared(p);
}
__device__ __forceinline__ void cp_async16(uint32_t dst, const float* src) {
    asm volatile("cp.async.ca.shared.global [%0], [%1], 16;\n" :: "r"(dst), "l"(src));
}

__device__ __forceinline__ bool f2_pred(float p, float upx, float k_up) {
    return __fadd_rn(p, -upx) <= k_up;          // fl(p - upx) <= k_up (monotone in p)
}
__device__ __forceinline__ void mkconst(const Wt& w, float xv,
                                        float& lo, float& upx, float& ub, float& v1) {
    float mlx = __fmul_rn(w.m_lo, xv);
    upx = __fmul_rn(w.m_up, xv);
    lo  = __fadd_rn(mlx, w.k_lo);
    ub  = __fadd_rn(upx, w.k_up);
    v1  = __fadd_rn(__fadd_rn(lo, upx), w.k_up); // reference's left-assoc sum
}
__device__ __forceinline__ float step1(float p, float lo, float upx, float ub,
                                       float v1, float k_up) {
    bool f1 = (p >= lo);
    bool f2 = f2_pred(p, upx, k_up);
    float a = f2 ? v1 : lo;
    float b = f2 ? ub : p;
    return f1 ? a : b;
}
// Largest float strictly below a (branchless; a finite, not NaN).
__device__ __forceinline__ float next_below(float a) {
    unsigned u   = __float_as_uint(a);
    unsigned stp = ((int)u >= 0) ? 0xFFFFFFFFu : 1u;   // -1 if sign bit clear
    unsigned v   = u + stp;
    v = (a == 0.0f) ? 0x80000001u : v;                 // +-0 -> smallest neg denorm
    return __uint_as_float(v);
}

__global__ __launch_bounds__(NT)
void backlash_chunks(const float* __restrict__ x,
                     const float* __restrict__ p0,
                     const float* __restrict__ wv,
                     float* __restrict__ out, int T)
{
    __shared__ float s_buf[NT * PAD];   // in/out aliased row buffer
    __shared__ float s_cv[NT];          // collapsed end-of-chunk value
    __shared__ int   s_sx[NT];          // collapse index (CL => never collapsed)
    __shared__ float s_in[NT];          // fallback: resolved incoming prev

    const int k   = threadIdx.x;
    const int row = blockIdx.x;
    const int F4  = T / (NT * 4);       // float4s per thread in coop copies (= 8)

    Wt w;
    w.m_lo = wv[0];
    w.m_up = wv[1];
    w.k_lo = __fmul_rn(w.m_lo, wv[2]);
    w.k_up = __fmul_rn(w.m_up, wv[3]);

    // ---- Coalesced staged load of the whole row (chunk-padded layout) ----
    {
        const float* src = x + (size_t)row * T;
        const uint32_t sb = smem_u32(s_buf);
        #pragma unroll
        for (int i = 0; i < F4; ++i) {
            int t = i * (NT * 4) + k * 4;
            int c = t / CL, o = t % CL;
            cp_async16(sb + (uint32_t)(c * PAD + o) * 4u, src + t);
        }
        asm volatile("cp.async.commit_group;\n" ::: "memory");
        asm volatile("cp.async.wait_group 0;\n" ::: "memory");
    }
    __syncthreads();

    float* xc = s_buf + k * PAD;        // this thread's chunk (in; becomes out)
    const float INF = __int_as_float(0x7f800000);

    // ---- Phase 1a: interval scan until collapse (no stores) ----
    float A = -INF, B = INF;
    float p = 0.0f;
    bool  done = false;
    int   t = 0;

    #pragma unroll 1
    for (; t < CL; ++t) {
        float lo, upx, ub, v1;
        mkconst(w, xc[t], lo, upx, ub, v1);
        // Region reachability over [A,B]: endpoint evals of the exact concrete
        // predicates -> collapse decisions are exact.
        float mAlo = fmaxf(A, lo);
        bool c1 = (mAlo <= B) &&  f2_pred(mAlo, upx, w.k_up); // f1& f2 -> v1
        bool c2 = (B >= lo)   && !f2_pred(B,    upx, w.k_up); // f1&!f2 -> lo
        bool c3 = (A <  lo)   &&  f2_pred(A,    upx, w.k_up); //!f1& f2 -> ub
        float ps = fminf(B, next_below(lo));
        bool c4 = (ps >= A)   && !f2_pred(ps,   upx, w.k_up); // identity lives
        float nA = INF, nB = -INF;
        if (c1) { nA = fminf(nA, v1); nB = fmaxf(nB, v1); }
        if (c2) { nA = fminf(nA, lo); nB = fmaxf(nB, lo); }
        if (c3) { nA = fminf(nA, ub); nB = fmaxf(nB, ub); }
        if (c4) { nA = fminf(nA, A);  nB = fmaxf(nB, ps); }
        A = nA; B = nB;
        if (A == B) { done = true; p = A; break; }
    }
    const int s = t;                    // collapse index, or CL if never

    // ---- Phase 1b: concrete scan, unconditional in-place stores (t >= s) ----
    if (done) {
        xc[s] = p;
        int u = s + 1;
        for (; u < CL && (u & 3); ++u) {           // align to float4
            float lo, upx, ub, v1;
            mkconst(w, xc[u], lo, upx, ub, v1);
            p = step1(p, lo, upx, ub, v1, w.k_up);
            xc[u] = p;
        }
        for (; u < CL; u += 4) {
            float4 q = *(const float4*)(xc + u);
            float lo, upx, ub, v1;
            mkconst(w, q.x, lo, upx, ub, v1);
            float o0 = step1(p,  lo, upx, ub, v1, w.k_up);
            mkconst(w, q.y, lo, upx, ub, v1);
            float o1 = step1(o0, lo, upx, ub, v1, w.k_up);
            mkconst(w, q.z, lo, upx, ub, v1);
            float o2 = step1(o1, lo, upx, ub, v1, w.k_up);
            mkconst(w, q.w, lo, upx, ub, v1);
            float o3 = step1(o2, lo, upx, ub, v1, w.k_up);
            p = o3;
            *(float4*)(xc + u) = make_float4(o0, o1, o2, o3);
        }
    }

    // ---- Phase 2: inter-chunk resolution ----
    s_cv[k] = p;
    s_sx[k] = s;
    bool all = (bool)__syncthreads_and((int)done);   // block-uniform barrier
    float pin;
    if (all) {
        pin = (k == 0) ? p0[row] : s_cv[k - 1];      // O(1) fast path
    } else {
        if (k == 0) {                                 // rare serial fallback
            float prev = p0[row];
            for (int c = 0; c < NT; ++c) {
                s_in[c] = prev;
                if (s_sx[c] < CL) {
                    prev = s_cv[c];
                } else {                              // chunk input untouched
                    const float* xr = s_buf + c * PAD;
                    for (int tt = 0; tt < CL; ++tt) {
                        float lo, upx, ub, v1;
                        mkconst(w, xr[tt], lo, upx, ub, v1);
                        prev = step1(prev, lo, upx, ub, v1, w.k_up);
                    }
                }
            }
        }
        __syncthreads();
        pin = s_in[k];
    }

    // ---- Phase 3: replay short pre-collapse prefix with the true state ----
    #pragma unroll 1
    for (int tt = 0; tt < s; ++tt) {
        float lo, upx, ub, v1;
        mkconst(w, xc[tt], lo, upx, ub, v1);
        pin = step1(pin, lo, upx, ub, v1, w.k_up);
        xc[tt] = pin;
    }
    __syncthreads();

    // ---- Coalesced staged store of the whole row ----
    {
        float* dst = out + (size_t)row * T;
        #pragma unroll
        for (int i = 0; i < F4; ++i) {
            int tg = i * (NT * 4) + k * 4;
            int c = tg / CL, o = tg % CL;
            float4 v = *(const float4*)(s_buf + c * PAD + o);
            *(float4*)(dst + tg) = v;
        }
    }
}

extern "C" void kernel_launch(void* const* d_in, const int* in_sizes, int n_in,
                              void* d_out, int out_size)
{
    const float* x  = (const float*)d_in[0];  // (B, T, 1) fp32
    const float* p0 = (const float*)d_in[1];  // (B, 1, 1) fp32
    const float* wv = (const float*)d_in[2];  // (4,)      fp32
    float* out = (float*)d_out;

    const int B = in_sizes[1];      // 2048
    const int T = in_sizes[0] / B;  // 8192  (= NT * CL)

    backlash_chunks<<<B, NT>>>(x, p0, wv, out, T);
}

// round 7
// speedup vs baseline: 10.5969x; 1.0487x over previous
#include <cuda_runtime.h>
#include <cstdint>
#include <cstddef>

// BacklashNet chunk-parallel scan: warp-decoupled SMEM staging, interval collapse.
//   lo = fl(fl(m_lo*x) + fl(m_lo*c_lo)), upx = fl(m_up*x), ub = fl(upx + k_up)
//   f1 = (prev >= lo);  f2 = (fl(prev - upx) <= k_up)
//   out = f1 ? (f2 ? fl(fl(lo+upx)+k_up) : lo) : (f2 ? ub : prev)
// Identity branch needs prev in (ub*, lo): interval-tracked until it provably
// collapses to one value -> chunk outputs become state-independent.

#define NT   256          // threads per block = chunks per row
#define CL   32           // steps per chunk (T = NT*CL = 8192)
#define PAD  36           // smem floats per chunk: 144B stride, 16B aligned;
                          //   pad slots [32..35] host per-chunk side data
#define WREG 1024         // floats per warp region (32 lanes * CL)

struct Wt { float m_lo, m_up, k_lo, k_up; };

__device__ __forceinline__ uint32_t smem_u32(const void* p) {
    return (uint32_t)__cvta_generic_to_shared(p);
}
__device__ __forceinline__ void cp_async16(uint32_t dst, const float* src) {
    asm volatile("cp.async.ca.shared.global [%0], [%1], 16;\n" :: "r"(dst), "l"(src));
}

__device__ __forceinline__ bool f2_pred(float p, float upx, float k_up) {
    return __fadd_rn(p, -upx) <= k_up;          // fl(p - upx) <= k_up (monotone in p)
}
__device__ __forceinline__ void mkconst(const Wt& w, float xv,
                                        float& lo, float& upx, float& ub, float& v1) {
    float mlx = __fmul_rn(w.m_lo, xv);
    upx = __fmul_rn(w.m_up, xv);
    lo  = __fadd_rn(mlx, w.k_lo);
    ub  = __fadd_rn(upx, w.k_up);
    v1  = __fadd_rn(__fadd_rn(lo, upx), w.k_up); // reference's left-assoc sum
}
__device__ __forceinline__ float step1(float p, float lo, float upx, float ub,
                                       float v1, float k_up) {
    bool f1 = (p >= lo);
    bool f2 = f2_pred(p, upx, k_up);
    float a = f2 ? v1 : lo;
    float b = f2 ? ub : p;
    return f1 ? a : b;
}
// Largest float strictly below a (branchless; a finite, not NaN).
__device__ __forceinline__ float next_below(float a) {
    unsigned u   = __float_as_uint(a);
    unsigned stp = ((int)u >= 0) ? 0xFFFFFFFFu : 1u;
    unsigned v   = u + stp;
    v = (a == 0.0f) ? 0x80000001u : v;
    return __uint_as_float(v);
}

__global__ __launch_bounds__(NT, 6)
void backlash_chunks(const float* __restrict__ x,
                     const float* __restrict__ p0,
                     const float* __restrict__ wv,
                     float* __restrict__ out, int T)
{
    __shared__ float s_buf[NT * PAD];   // chunk data + per-chunk pad slots:
                                        //   xc[32]=cv  xc[33]=sx(int)  xc[34]=in

    const int k    = threadIdx.x;
    const int wid  = k >> 5;            // warp id (0..7)
    const int lane = k & 31;

    Wt w;
    w.m_lo = wv[0];
    w.m_up = wv[1];
    w.k_lo = __fmul_rn(w.m_lo, wv[2]);
    w.k_up = __fmul_rn(w.m_up, wv[3]);

    const size_t rowbase = (size_t)blockIdx.x * T;

    // ---- Warp-local coalesced staged load: warp w owns chunks [32w, 32w+32) ----
    {
        const float* src = x + rowbase + wid * WREG;
        const uint32_t sb = smem_u32(s_buf);
        #pragma unroll
        for (int i = 0; i < 8; ++i) {
            int tl = i * 128 + lane * 4;            // [0, 1024) within warp region
            int c  = wid * 32 + (tl >> 5);
            int o  = tl & 31;
            cp_async16(sb + (uint32_t)(c * PAD + o) * 4u, src + tl);
        }
        asm volatile("cp.async.commit_group;\n" ::: "memory");
        asm volatile("cp.async.wait_group 0;\n" ::: "memory");
        __syncwarp();   // make cp.async data visible across the warp's lanes
    }

    float* xc = s_buf + k * PAD;        // this thread's chunk (in; becomes out)
    const float INF = __int_as_float(0x7f800000);

    // ---- Phase 1a: interval scan until collapse (no stores) ----
    float A = -INF, B = INF;
    float p = 0.0f;
    bool  done = false;
    int   t = 0;

    #pragma unroll 1
    for (; t < CL; ++t) {
        float lo, upx, ub, v1;
        mkconst(w, xc[t], lo, upx, ub, v1);
        // Region reachability over [A,B]: endpoint evals of the exact concrete
        // predicates -> collapse decisions are exact.
        float mAlo = fmaxf(A, lo);
        bool c1 = (mAlo <= B) &&  f2_pred(mAlo, upx, w.k_up); // f1& f2 -> v1
        bool c2 = (B >= lo)   && !f2_pred(B,    upx, w.k_up); // f1&!f2 -> lo
        bool c3 = (A <  lo)   &&  f2_pred(A,    upx, w.k_up); //!f1& f2 -> ub
        float ps = fminf(B, next_below(lo));
        bool c4 = (ps >= A)   && !f2_pred(ps,   upx, w.k_up); // identity lives
        float nA = INF, nB = -INF;
        if (c1) { nA = fminf(nA, v1); nB = fmaxf(nB, v1); }
        if (c2) { nA = fminf(nA, lo); nB = fmaxf(nB, lo); }
        if (c3) { nA = fminf(nA, ub); nB = fmaxf(nB, ub); }
        if (c4) { nA = fminf(nA, A);  nB = fmaxf(nB, ps); }
        A = nA; B = nB;
        if (A == B) { done = true; p = A; break; }
    }
    const int s = t;                    // collapse index, or CL if never

    // ---- Phase 1b: concrete scan, unconditional in-place stores (t >= s) ----
    if (done) {
        xc[s] = p;
        int u = s + 1;
        for (; u < CL && (u & 3); ++u) {
            float lo, upx, ub, v1;
            mkconst(w, xc[u], lo, upx, ub, v1);
            p = step1(p, lo, upx, ub, v1, w.k_up);
            xc[u] = p;
        }
        for (; u < CL; u += 4) {
            float4 q = *(const float4*)(xc + u);
            float lo, upx, ub, v1;
            mkconst(w, q.x, lo, upx, ub, v1);
            float o0 = step1(p,  lo, upx, ub, v1, w.k_up);
            mkconst(w, q.y, lo, upx, ub, v1);
            float o1 = step1(o0, lo, upx, ub, v1, w.k_up);
            mkconst(w, q.z, lo, upx, ub, v1);
            float o2 = step1(o1, lo, upx, ub, v1, w.k_up);
            mkconst(w, q.w, lo, upx, ub, v1);
            float o3 = step1(o2, lo, upx, ub, v1, w.k_up);
            p = o3;
            *(float4*)(xc + u) = make_float4(o0, o1, o2, o3);
        }
    }

    // ---- Phase 2: inter-chunk resolution (pad-slot side channel) ----
    xc[32] = p;                                  // collapsed end value
    reinterpret_cast<int*>(xc)[33] = s;          // collapse index
    bool all = (bool)__syncthreads_and((int)done);   // block-uniform barrier
    float pin;
    if (all) {
        pin = (k == 0) ? p0[blockIdx.x] : s_buf[(k - 1) * PAD + 32];
    } else {
        if (k == 0) {                             // rare serial fallback
            float prev = p0[blockIdx.x];
            for (int c = 0; c < NT; ++c) {
                float* xr = s_buf + c * PAD;
                xr[34] = prev;
                if (reinterpret_cast<int*>(xr)[33] < CL) {
                    prev = xr[32];
                } else {                          // chunk input untouched
                    for (int tt = 0; tt < CL; ++tt) {
                        float lo, upx, ub, v1;
                        mkconst(w, xr[tt], lo, upx, ub, v1);
                        prev = step1(prev, lo, upx, ub, v1, w.k_up);
                    }
                }
            }
        }
        __syncthreads();
        pin = xc[34];
    }

    // ---- Phase 3: replay short pre-collapse prefix with the true state ----
    #pragma unroll 1
    for (int tt = 0; tt < s; ++tt) {
        float lo, upx, ub, v1;
        mkconst(w, xc[tt], lo, upx, ub, v1);
        pin = step1(pin, lo, upx, ub, v1, w.k_up);
        xc[tt] = pin;
    }

    // ---- Warp-local coalesced store: warp w's chunks are final once its own
    //      lanes finish phase 3 (no block barrier needed) ----
    __syncwarp();
    {
        float* dst = out + rowbase + wid * WREG;
        #pragma unroll
        for (int i = 0; i < 8; ++i) {
            int tl = i * 128 + lane * 4;
            int c  = wid * 32 + (tl >> 5);
            int o  = tl & 31;
            float4 v = *(const float4*)(s_buf + c * PAD + o);
            *(float4*)(dst + tl) = v;
        }
    }
}

extern "C" void kernel_launch(void* const* d_in, const int* in_sizes, int n_in,
                              void* d_out, int out_size)
{
    const float* x  = (const float*)d_in[0];  // (B, T, 1) fp32
    const float* p0 = (const float*)d_in[1];  // (B, 1, 1) fp32
    const float* wv = (const float*)d_in[2];  // (4,)      fp32
    float* out = (float*)d_out;

    const int B = in_sizes[1];      // 2048
    const int T = in_sizes[0] / B;  // 8192  (= NT * CL)

    backlash_chunks<<<B, NT>>>(x, p0, wv, out, T);
}

// round 8
// speedup vs baseline: 11.1958x; 1.0565x over previous
#include <cuda_runtime.h>
#include <cstdint>
#include <cstddef>

// BacklashNet chunk-parallel scan: warp-decoupled SMEM staging, interval collapse.
//   lo = fl(fl(m_lo*x) + fl(m_lo*c_lo)), upx = fl(m_up*x), ub = fl(upx + k_up)
//   f1 = (prev >= lo);  f2 = (fl(prev - upx) <= k_up)
//   out = f1 ? (f2 ? fl(fl(lo+upx)+k_up) : lo) : (f2 ? ub : prev)
// Identity branch needs prev in (ub*, lo): interval-tracked until it provably
// collapses to one value -> chunk outputs become state-independent.

#define NT   512          // threads per block = chunks per row
#define CL   16           // steps per chunk (T = NT*CL = 8192)
#define PAD  20           // smem floats per chunk: 80B stride, 16B aligned;
                          //   conflict-free for 128-bit LDS/STS; slots [16..19]
#define WREG 512          // floats per warp region (32 lanes * CL)

struct Wt { float m_lo, m_up, k_lo, k_up; };

__device__ __forceinline__ uint32_t smem_u32(const void* p) {
    return (uint32_t)__cvta_generic_to_shared(p);
}
__device__ __forceinline__ void cp_async16(uint32_t dst, const float* src) {
    asm volatile("cp.async.ca.shared.global [%0], [%1], 16;\n" :: "r"(dst), "l"(src));
}

__device__ __forceinline__ bool f2_pred(float p, float upx, float k_up) {
    return __fadd_rn(p, -upx) <= k_up;          // fl(p - upx) <= k_up (monotone in p)
}
__device__ __forceinline__ void mkconst(const Wt& w, float xv,
                                        float& lo, float& upx, float& ub, float& v1) {
    float mlx = __fmul_rn(w.m_lo, xv);
    upx = __fmul_rn(w.m_up, xv);
    lo  = __fadd_rn(mlx, w.k_lo);
    ub  = __fadd_rn(upx, w.k_up);
    v1  = __fadd_rn(__fadd_rn(lo, upx), w.k_up); // reference's left-assoc sum
}
__device__ __forceinline__ float step1(float p, float lo, float upx, float ub,
                                       float v1, float k_up) {
    bool f1 = (p >= lo);
    bool f2 = f2_pred(p, upx, k_up);
    float a = f2 ? v1 : lo;
    float b = f2 ? ub : p;
    return f1 ? a : b;
}
// Largest float strictly below a (branchless; a finite, not NaN).
__device__ __forceinline__ float next_below(float a) {
    unsigned u   = __float_as_uint(a);
    unsigned stp = ((int)u >= 0) ? 0xFFFFFFFFu : 1u;
    unsigned v   = u + stp;
    v = (a == 0.0f) ? 0x80000001u : v;
    return __uint_as_float(v);
}

__global__ __launch_bounds__(NT, 3)
void backlash_chunks(const float* __restrict__ x,
                     const float* __restrict__ p0,
                     const float* __restrict__ wv,
                     float* __restrict__ out, int T)
{
    __shared__ float s_buf[NT * PAD];   // chunk data + pad slots:
                                        //   xc[16]=cv  xc[17]=sx(int)  xc[18]=in

    const int k    = threadIdx.x;
    const int wid  = k >> 5;            // warp id (0..15)
    const int lane = k & 31;

    Wt w;
    w.m_lo = wv[0];
    w.m_up = wv[1];
    w.k_lo = __fmul_rn(w.m_lo, wv[2]);
    w.k_up = __fmul_rn(w.m_up, wv[3]);

    const size_t rowbase = (size_t)blockIdx.x * T;

    // ---- Warp-local coalesced staged load: warp w owns chunks [32w, 32w+32) ----
    {
        const float* src = x + rowbase + wid * WREG;
        const uint32_t sb = smem_u32(s_buf);
        #pragma unroll
        for (int i = 0; i < 4; ++i) {
            int tl = i * 128 + lane * 4;            // [0, 512) within warp region
            int c  = wid * 32 + (tl >> 4);
            int o  = tl & 15;
            cp_async16(sb + (uint32_t)(c * PAD + o) * 4u, src + tl);
        }
        asm volatile("cp.async.commit_group;\n" ::: "memory");
        asm volatile("cp.async.wait_group 0;\n" ::: "memory");
        __syncwarp();   // make cp.async data visible across the warp's lanes
    }

    float* xc = s_buf + k * PAD;        // this thread's chunk (in; becomes out)
    const float INF = __int_as_float(0x7f800000);

    // ---- Phase 1a: interval scan until collapse (float4 group loads, no stores) ----
    float A = -INF, B = INF;
    float p = 0.0f;
    bool  done = false;
    int   s = CL;

    #pragma unroll 1
    for (int t4 = 0; t4 < CL && !done; t4 += 4) {
        float4 q = *(const float4*)(xc + t4);
        float xs[4] = {q.x, q.y, q.z, q.w};
        #pragma unroll
        for (int j = 0; j < 4; ++j) {
            if (!done) {
                float lo, upx, ub, v1;
                mkconst(w, xs[j], lo, upx, ub, v1);
                // Region reachability over [A,B]: endpoint evals of the exact
                // concrete predicates -> collapse decisions are exact.
                float mAlo = fmaxf(A, lo);
                bool c1 = (mAlo <= B) &&  f2_pred(mAlo, upx, w.k_up); // f1& f2 -> v1
                bool c2 = (B >= lo)   && !f2_pred(B,    upx, w.k_up); // f1&!f2 -> lo
                bool c3 = (A <  lo)   &&  f2_pred(A,    upx, w.k_up); //!f1& f2 -> ub
                float ps = fminf(B, next_below(lo));
                bool c4 = (ps >= A)   && !f2_pred(ps,   upx, w.k_up); // identity
                float nA = INF, nB = -INF;
                if (c1) { nA = fminf(nA, v1); nB = fmaxf(nB, v1); }
                if (c2) { nA = fminf(nA, lo); nB = fmaxf(nB, lo); }
                if (c3) { nA = fminf(nA, ub); nB = fmaxf(nB, ub); }
                if (c4) { nA = fminf(nA, A);  nB = fmaxf(nB, ps); }
                A = nA; B = nB;
                if (A == B) { done = true; p = A; s = t4 + j; }
            }
        }
    }

    // ---- Phase 1b: concrete scan, unconditional in-place stores (t >= s) ----
    if (done) {
        xc[s] = p;
        int u = s + 1;
        for (; u < CL && (u & 3); ++u) {           // align to float4
            float lo, upx, ub, v1;
            mkconst(w, xc[u], lo, upx, ub, v1);
            p = step1(p, lo, upx, ub, v1, w.k_up);
            xc[u] = p;
        }
        #pragma unroll 1
        for (; u < CL; u += 4) {
            float4 q = *(const float4*)(xc + u);
            float lo, upx, ub, v1;
            mkconst(w, q.x, lo, upx, ub, v1);
            float o0 = step1(p,  lo, upx, ub, v1, w.k_up);
            mkconst(w, q.y, lo, upx, ub, v1);
            float o1 = step1(o0, lo, upx, ub, v1, w.k_up);
            mkconst(w, q.z, lo, upx, ub, v1);
            float o2 = step1(o1, lo, upx, ub, v1, w.k_up);
            mkconst(w, q.w, lo, upx, ub, v1);
            float o3 = step1(o2, lo, upx, ub, v1, w.k_up);
            p = o3;
            *(float4*)(xc + u) = make_float4(o0, o1, o2, o3);
        }
    }

    // ---- Phase 2: inter-chunk resolution (pad-slot side channel) ----
    xc[16] = p;                                  // collapsed end value
    reinterpret_cast<int*>(xc)[17] = s;          // collapse index
    bool all = (bool)__syncthreads_and((int)done);   // block-uniform barrier
    float pin;
    if (all) {
        pin = (k == 0) ? p0[blockIdx.x] : s_buf[(k - 1) * PAD + 16];
    } else {
        if (k == 0) {                             // rare serial fallback
            float prev = p0[blockIdx.x];
            for (int c = 0; c < NT; ++c) {
                float* xr = s_buf + c * PAD;
                xr[18] = prev;
                if (reinterpret_cast<int*>(xr)[17] < CL) {
                    prev = xr[16];
                } else {                          // chunk input untouched
                    for (int tt = 0; tt < CL; ++tt) {
                        float lo, upx, ub, v1;
                        mkconst(w, xr[tt], lo, upx, ub, v1);
                        prev = step1(prev, lo, upx, ub, v1, w.k_up);
                    }
                }
            }
        }
        __syncthreads();
        pin = xc[18];
    }

    // ---- Phase 3: replay short pre-collapse prefix with the true state ----
    #pragma unroll 1
    for (int tt = 0; tt < s; ++tt) {
        float lo, upx, ub, v1;
        mkconst(w, xc[tt], lo, upx, ub, v1);
        pin = step1(pin, lo, upx, ub, v1, w.k_up);
        xc[tt] = pin;
    }

    // ---- Warp-local coalesced store: warp w's chunks are final once its own
    //      lanes finish phase 3 (no block barrier needed) ----
    __syncwarp();
    {
        float* dst = out + rowbase + wid * WREG;
        #pragma unroll
        for (int i = 0; i < 4; ++i) {
            int tl = i * 128 + lane * 4;
            int c  = wid * 32 + (tl >> 4);
            int o  = tl & 15;
            float4 v = *(const float4*)(s_buf + c * PAD + o);
            *(float4*)(dst + tl) = v;
        }
    }
}

extern "C" void kernel_launch(void* const* d_in, const int* in_sizes, int n_in,
                              void* d_out, int out_size)
{
    const float* x  = (const float*)d_in[0];  // (B, T, 1) fp32
    const float* p0 = (const float*)d_in[1];  // (B, 1, 1) fp32
    const float* wv = (const float*)d_in[2];  // (4,)      fp32
    float* out = (float*)d_out;

    const int B = in_sizes[1];      // 2048
    const int T = in_sizes[0] / B;  // 8192  (= NT * CL)

    backlash_chunks<<<B, NT>>>(x, p0, wv, out, T);
}